// round 9
// baseline (speedup 1.0000x reference)
#include <cuda_runtime.h>
#include <cuda_bf16.h>
#include <cstdint>

// ============================================================================
// out_f32[m, n] = f32( bf16(sum_k bf16(x[m,k]) * (bf16(w_fp8[n,k])*bf16(sc[n]))) + bf16(bias[n]) )
// M = B*S = 4096, N = OUT = 4096, K = IN = 4096. OUTPUT IS FP32 (root cause of
// rounds 6-8: we wrote bf16 into an fp32 buffer -> rel_err = sqrt(1.5)).
// (1) convert x -> bf16 scratch, (2) dequantize w -> bf16 scratch,
// (3) tcgen05 bf16 GEMM, 128x128 tiles, TS mode (A in TMEM), B via 5-stage
//     cp.async pipeline, commit+wait per K-chunk. ~81KB SMEM -> 2 CTAs/SM.
// tcgen05 only in the arch-specific pass; generic pass gets a scalar fallback.
// ============================================================================

#if defined(__CUDA_ARCH__) && \
    (defined(__CUDA_ARCH_FEAT_SM103_ALL) || defined(__CUDA_ARCH_FEAT_SM100_ALL) || \
     defined(__CUDA_ARCH_FEAT_SM101_ALL) || defined(__CUDA_ARCH_SPECIFIC__) || \
     defined(__CUDA_ARCH_FAMILY_SPECIFIC__))
#define HAS_TCGEN05 1
#else
#define HAS_TCGEN05 0
#endif

static constexpr int Mdim = 4096, Ndim = 4096, Kdim = 4096;
static constexpr int MT = 128, NT = 128, KC = 64;        // tile sizes; KC=64 bf16=128B
static constexpr int STAGES = 5;                          // B pipeline stages
static constexpr int NCHUNK = Kdim / KC;                  // 64
static constexpr int STAGE_BYTES = 128 * 128;             // 128 B-rows x 128B

static constexpr int SMEM_TMEM_PTR = 0;
static constexpr int SMEM_MBAR = 64;                      // one 8B mbarrier
static constexpr int SMEM_B = 1024;
static constexpr int SMEM_TOTAL = SMEM_B + STAGES * STAGE_BYTES;  // ~81 KB -> 2 CTAs/SM

// TMEM layout: D fp32 at cols [0,128); A double-buffer at cols [128,192).
static constexpr int TMEM_COLS_ALLOC = 256;
static constexpr int TMEM_D = 0;
static constexpr int TMEM_A = 128;                        // + (chunk&1)*32

// idesc kind::f16, N=64 per dispatch: dtype=F32(1<<4), atype=BF16(1<<7),
// btype=BF16(1<<10), N>>3 at [17:23), M>>4 at [24:29).  M=128,N=64 -> 0x8100490
static constexpr uint32_t IDESC64 =
    (1u << 4) | (1u << 7) | (1u << 10) | ((64 / 8) << 17) | ((MT / 16) << 24);

// B rows 64..127 start at byte 64/8 * 1024 = 8192 -> 512 descriptor units (16B).
static constexpr uint32_t BDESC_HALF_OFF = 8192 / 16;

// bf16 scratch (allowed: __device__ global arrays)
__device__ __nv_bfloat16 g_x[(size_t)Mdim * Kdim];
__device__ __nv_bfloat16 g_w[(size_t)Ndim * Kdim];

// ============================================================================
// PTX helpers
// ============================================================================

__device__ __forceinline__ uint32_t smem_u32(const void* p) {
    uint32_t a;
    asm("{ .reg .u64 t; cvta.to.shared.u64 t, %1; cvt.u32.u64 %0, t; }"
        : "=r"(a) : "l"(p));
    return a;
}

__device__ __forceinline__ void cp_async16(uint32_t s, const void* g) {
    asm volatile("cp.async.cg.shared.global [%0], [%1], 16;" :: "r"(s), "l"(g));
}
__device__ __forceinline__ void cp_commit() {
    asm volatile("cp.async.commit_group;" ::: "memory");
}
template <int N>
__device__ __forceinline__ void cp_wait() {
    asm volatile("cp.async.wait_group %0;" :: "n"(N) : "memory");
}

#if HAS_TCGEN05
__device__ __forceinline__ uint32_t elect_one() {
    uint32_t pred;
    asm volatile(
        "{\n\t.reg .pred p;\n\t"
        "elect.sync _|p, 0xFFFFFFFF;\n\t"
        "selp.b32 %0, 1, 0, p;\n\t}"
        : "=r"(pred));
    return pred;
}

__device__ __forceinline__ void mbar_init(uint32_t addr, uint32_t count) {
    asm volatile("mbarrier.init.shared.b64 [%0], %1;" :: "r"(addr), "r"(count) : "memory");
}
__device__ __forceinline__ void mbar_inval(uint32_t addr) {
    asm volatile("mbarrier.inval.shared.b64 [%0];" :: "r"(addr) : "memory");
}
__device__ __forceinline__ void mbar_wait(uint32_t addr, uint32_t parity) {
    asm volatile(
        "{\n\t.reg .pred P;\n\t"
        "WAIT_%=:\n\t"
        "mbarrier.try_wait.parity.acquire.cta.shared::cta.b64 P, [%0], %1, 0x989680;\n\t"
        "@P bra DONE_%=;\n\t"
        "bra WAIT_%=;\n\t"
        "DONE_%=:\n\t}"
        :: "r"(addr), "r"(parity) : "memory");
}

__device__ __forceinline__ void fence_proxy_async_cta() {
    asm volatile("fence.proxy.async.shared::cta;" ::: "memory");
}

// SW128 K-major descriptor: layout=2, version=1, SBO=64, LBO=1
__device__ __forceinline__ uint64_t make_desc(uint32_t addr) {
    const uint64_t base =
        (uint64_t(2) << 61) | (uint64_t(1) << 46) | (uint64_t(64) << 32) | (uint64_t(1) << 16);
    return base | ((uint64_t)(addr >> 4) & 0x3FFF);
}

// TS-mode MMA: A in TMEM, B via SMEM descriptor.
__device__ __forceinline__ void mma_f16_ts(uint32_t d_tmem, uint32_t a_tmem, uint64_t b_desc,
                                           uint32_t idesc, uint32_t enable) {
    uint32_t zero = 0;
    asm volatile(
        "{\n\t.reg .pred p;\n\t"
        "setp.ne.u32 p, %4, 0;\n\t"
        "tcgen05.mma.cta_group::1.kind::f16 [%0], [%1], %2, %3, {%5, %5, %5, %5}, p;\n\t}"
        :: "r"(d_tmem), "r"(a_tmem), "l"(b_desc), "r"(idesc), "r"(enable), "r"(zero)
        : "memory");
}

__device__ __forceinline__ void tc_commit(uint32_t mbar) {
    asm volatile(
        "tcgen05.commit.cta_group::1.mbarrier::arrive::one.shared::cluster.b64 [%0];"
        :: "r"(mbar) : "memory");
}

#define TC_ALLOC(smem_addr, ncols) \
    asm volatile("tcgen05.alloc.cta_group::1.sync.aligned.shared::cta.b32 [%0], %1;" \
                 :: "r"(smem_addr), "r"((uint32_t)(ncols)) : "memory")
#define TC_DEALLOC(tmem, ncols) \
    asm volatile("tcgen05.dealloc.cta_group::1.sync.aligned.b32 %0, %1;" \
                 :: "r"(tmem), "r"((uint32_t)(ncols)))
#define TC_RELINQUISH() \
    asm volatile("tcgen05.relinquish_alloc_permit.cta_group::1.sync.aligned;")
#define TC_FENCE_AFTER() asm volatile("tcgen05.fence::after_thread_sync;" ::: "memory")
#define TC_FENCE_BEFORE() asm volatile("tcgen05.fence::before_thread_sync;" ::: "memory")
#define TC_WAIT_LD() asm volatile("tcgen05.wait::ld.sync.aligned;" ::: "memory")
#define TC_WAIT_ST() asm volatile("tcgen05.wait::st.sync.aligned;" ::: "memory")

#define LDTM_X32(r, addr) \
    asm volatile( \
        "tcgen05.ld.sync.aligned.32x32b.x32.b32 " \
        "{%0, %1, %2, %3, %4, %5, %6, %7, " \
        " %8, %9, %10, %11, %12, %13, %14, %15, " \
        " %16, %17, %18, %19, %20, %21, %22, %23, " \
        " %24, %25, %26, %27, %28, %29, %30, %31}, [%32];" \
        : "=r"((r)[0]),  "=r"((r)[1]),  "=r"((r)[2]),  "=r"((r)[3]), \
          "=r"((r)[4]),  "=r"((r)[5]),  "=r"((r)[6]),  "=r"((r)[7]), \
          "=r"((r)[8]),  "=r"((r)[9]),  "=r"((r)[10]), "=r"((r)[11]), \
          "=r"((r)[12]), "=r"((r)[13]), "=r"((r)[14]), "=r"((r)[15]), \
          "=r"((r)[16]), "=r"((r)[17]), "=r"((r)[18]), "=r"((r)[19]), \
          "=r"((r)[20]), "=r"((r)[21]), "=r"((r)[22]), "=r"((r)[23]), \
          "=r"((r)[24]), "=r"((r)[25]), "=r"((r)[26]), "=r"((r)[27]), \
          "=r"((r)[28]), "=r"((r)[29]), "=r"((r)[30]), "=r"((r)[31]) \
        : "r"(addr))

#define STTM_X32(addr, r) \
    asm volatile( \
        "tcgen05.st.sync.aligned.32x32b.x32.b32 [%0], " \
        "{%1, %2, %3, %4, %5, %6, %7, %8, " \
        " %9, %10, %11, %12, %13, %14, %15, %16, " \
        " %17, %18, %19, %20, %21, %22, %23, %24, " \
        " %25, %26, %27, %28, %29, %30, %31, %32};" \
        :: "r"(addr), \
           "r"((r)[0]),  "r"((r)[1]),  "r"((r)[2]),  "r"((r)[3]), \
           "r"((r)[4]),  "r"((r)[5]),  "r"((r)[6]),  "r"((r)[7]), \
           "r"((r)[8]),  "r"((r)[9]),  "r"((r)[10]), "r"((r)[11]), \
           "r"((r)[12]), "r"((r)[13]), "r"((r)[14]), "r"((r)[15]), \
           "r"((r)[16]), "r"((r)[17]), "r"((r)[18]), "r"((r)[19]), \
           "r"((r)[20]), "r"((r)[21]), "r"((r)[22]), "r"((r)[23]), \
           "r"((r)[24]), "r"((r)[25]), "r"((r)[26]), "r"((r)[27]), \
           "r"((r)[28]), "r"((r)[29]), "r"((r)[30]), "r"((r)[31]) \
        : "memory")
#endif  // HAS_TCGEN05

// ============================================================================
// Conversion kernels (arch-neutral)
// ============================================================================

__global__ void __launch_bounds__(256) cvt_x_kernel(const float* __restrict__ x) {
    size_t i = ((size_t)blockIdx.x * blockDim.x + threadIdx.x) * 4;
    float4 v = *reinterpret_cast<const float4*>(x + i);
    *reinterpret_cast<__nv_bfloat162*>(&g_x[i])     = __floats2bfloat162_rn(v.x, v.y);
    *reinterpret_cast<__nv_bfloat162*>(&g_x[i + 2]) = __floats2bfloat162_rn(v.z, v.w);
}

__global__ void __launch_bounds__(256) cvt_w_kernel(const float* __restrict__ wq,
                                                    const float* __restrict__ sc) {
    size_t i = ((size_t)blockIdx.x * blockDim.x + threadIdx.x) * 4;
    int o = (int)(i >> 12);  // row = i / 4096
    __nv_bfloat16 s = __float2bfloat16(sc[o]);
    float4 v = *reinterpret_cast<const float4*>(wq + i);
    __nv_bfloat16 h0 = __hmul(__float2bfloat16(v.x), s);
    __nv_bfloat16 h1 = __hmul(__float2bfloat16(v.y), s);
    __nv_bfloat16 h2 = __hmul(__float2bfloat16(v.z), s);
    __nv_bfloat16 h3 = __hmul(__float2bfloat16(v.w), s);
    *reinterpret_cast<__nv_bfloat162*>(&g_w[i])     = __halves2bfloat162(h0, h1);
    *reinterpret_cast<__nv_bfloat162*>(&g_w[i + 2]) = __halves2bfloat162(h2, h3);
}

// ============================================================================
// GEMM kernel: 128x128 tile per CTA, TS-mode A, FP32 output.
// ============================================================================

__global__ void __launch_bounds__(128) gemm_kernel(float* __restrict__ out,
                                                   const float* __restrict__ bias) {
    extern __shared__ char smem[];
    int tid = threadIdx.x;
    int n0 = blockIdx.x * NT;
    int m0 = blockIdx.y * MT;

#if HAS_TCGEN05
    uint32_t sb = smem_u32(smem);
    int wid = tid >> 5;
    int lid = tid & 31;
    uint32_t warp_off = (uint32_t)(tid >> 5) << 21;   // TMEM lane-base for ST

    if (tid == 0) mbar_init(sb + SMEM_MBAR, 1);
    // ONLY warp 0 touches the TMEM allocation permit.
    if (wid == 0) {
        TC_ALLOC(sb + SMEM_TMEM_PTR, TMEM_COLS_ALLOC);
    }
    __syncthreads();
    uint32_t tmem;
    asm volatile("ld.shared.b32 %0, [%1];" : "=r"(tmem) : "r"(sb + SMEM_TMEM_PTR));

    // Thread t owns A row m0+t (64 bf16 per chunk -> 32 bf16x2 regs -> TMEM)
    // and B row n0+t (cp.async 128B per chunk into swizzled SMEM).
    const __nv_bfloat16* xrow = g_x + (size_t)(m0 + tid) * Kdim;
    const __nv_bfloat16* wrow = g_w + (size_t)(n0 + tid) * Kdim;
    uint32_t swoff[8];
    #pragma unroll
    for (int j = 0; j < 8; j++) {
        uint32_t off = (uint32_t)tid * 128 + j * 16;
        swoff[j] = off ^ ((off >> 3) & 0x70);
    }

    auto load_b = [&](int c) {
        uint32_t bbase = sb + SMEM_B + (c % STAGES) * STAGE_BYTES;
        const __nv_bfloat16* wb = wrow + c * KC;
        #pragma unroll
        for (int j = 0; j < 8; j++) cp_async16(bbase + swoff[j], wb + j * 8);
        cp_commit();
    };

    auto load_a_regs = [&](int c, uint32_t* r) {
        const uint4* src = reinterpret_cast<const uint4*>(xrow + c * KC);
        #pragma unroll
        for (int q = 0; q < 8; q++) {
            uint4 v = src[q];
            r[4 * q] = v.x; r[4 * q + 1] = v.y; r[4 * q + 2] = v.z; r[4 * q + 3] = v.w;
        }
    };

    // Prologue: A chunk 0 -> TMEM buf 0; A chunk 1 -> regs; B chunks 0..3 in flight.
    uint32_t aregs[32];
    load_a_regs(0, aregs);
    STTM_X32(tmem + TMEM_A + 0 + warp_off, aregs);
    TC_WAIT_ST();
    load_a_regs(1, aregs);
    load_b(0); load_b(1); load_b(2); load_b(3);

    for (int c = 0; c < NCHUNK; c++) {
        if (c + 4 < NCHUNK) load_b(c + 4);

        // Stage A chunk c+1 into the other TMEM buffer (chunk c-1's MMA, which
        // read it, completed at the end of iteration c-1).
        if (c + 1 < NCHUNK) {
            STTM_X32(tmem + TMEM_A + ((c + 1) & 1) * 32 + warp_off, aregs);
            TC_WAIT_ST();
        }
        TC_FENCE_BEFORE();

        // Wait for B chunk c's cp.async group.
        int rem = NCHUNK - 1 - c;
        if (rem >= 4)      cp_wait<4>();
        else if (rem == 3) cp_wait<3>();
        else if (rem == 2) cp_wait<2>();
        else if (rem == 1) cp_wait<1>();
        else               cp_wait<0>();
        fence_proxy_async_cta();
        __syncthreads();

        if (wid == 0) {
            TC_FENCE_AFTER();
            uint64_t bd = make_desc(sb + SMEM_B + (c % STAGES) * STAGE_BYTES);
            uint32_t atm = tmem + TMEM_A + (c & 1) * 32;
            if (elect_one()) {
                #pragma unroll
                for (int kk = 0; kk < 4; kk++) {
                    // K-step: A cols kk*8 (16 bf16), B desc +kk*2 (32B).
                    // Two N=64 dispatches: D cols [0,64) <- B rows [0,64),
                    // D cols [64,128) <- B rows [64,128).
                    uint32_t en = (c == 0 && kk == 0) ? 0u : 1u;
                    mma_f16_ts(tmem + TMEM_D,      atm + kk * 8, bd + kk * 2,
                               IDESC64, en);
                    mma_f16_ts(tmem + TMEM_D + 64, atm + kk * 8, bd + kk * 2 + BDESC_HALF_OFF,
                               IDESC64, en);
                }
                tc_commit(sb + SMEM_MBAR);
            }
        }

        // Prefetch A chunk c+2 into registers while MMA runs.
        if (c + 2 < NCHUNK) load_a_regs(c + 2, aregs);

        // Wait for this chunk's MMAs to retire (parity = c&1).
        mbar_wait(sb + SMEM_MBAR, c & 1);
    }
    TC_FENCE_AFTER();

    // Epilogue (FP32 OUTPUT): each warp reads its 32-lane subpartition
    // (row = wid*32+lid). Reference semantics: bf16(acc) + bf16(bias) in bf16,
    // widened to f32 for storage.
    {
        int mrow = m0 + wid * 32 + lid;
        float* orow = out + (size_t)mrow * Ndim + n0;
        #pragma unroll
        for (int cb = 0; cb < NT; cb += 32) {
            uint32_t r[32];
            LDTM_X32(r, tmem + TMEM_D + cb);
            TC_WAIT_LD();
            float vals[32];
            #pragma unroll
            for (int j = 0; j < 32; j++) {
                __nv_bfloat16 s = __hadd(__float2bfloat16(__uint_as_float(r[j])),
                                         __float2bfloat16(bias[n0 + cb + j]));
                vals[j] = __bfloat162float(s);
            }
            float4* dst = reinterpret_cast<float4*>(orow + cb);
            #pragma unroll
            for (int q = 0; q < 8; q++) {
                dst[q] = make_float4(vals[4 * q], vals[4 * q + 1],
                                     vals[4 * q + 2], vals[4 * q + 3]);
            }
        }
    }

    __syncthreads();
    if (tid == 0) mbar_inval(sb + SMEM_MBAR);
    __syncthreads();
    if (wid == 0) {
        TC_RELINQUISH();
        TC_DEALLOC(tmem, TMEM_COLS_ALLOC);
    }
#else
    // ---------- Generic fallback (no tcgen05 in this compile pass) ----------
    __nv_bfloat16* As = reinterpret_cast<__nv_bfloat16*>(smem);            // 128 x 32
    __nv_bfloat16* Bs = As + 128 * 32;                                     // 128 x 32
    int tr = tid >> 3;   // 0..15 -> rows [tr*8, tr*8+8)
    int tc = tid & 7;    // 0..7  -> cols [tc*16, tc*16+16)

    float acc[8][16];
    #pragma unroll
    for (int i = 0; i < 8; i++)
        #pragma unroll
        for (int j = 0; j < 16; j++) acc[i][j] = 0.0f;

    for (int kc = 0; kc < Kdim; kc += 32) {
        const uint4* srcA = reinterpret_cast<const uint4*>(g_x + (size_t)(m0 + tid) * Kdim + kc);
        const uint4* srcB = reinterpret_cast<const uint4*>(g_w + (size_t)(n0 + tid) * Kdim + kc);
        uint4* dA = reinterpret_cast<uint4*>(As + tid * 32);
        uint4* dB = reinterpret_cast<uint4*>(Bs + tid * 32);
        #pragma unroll
        for (int j = 0; j < 4; j++) { dA[j] = srcA[j]; dB[j] = srcB[j]; }
        __syncthreads();

        for (int kk = 0; kk < 32; kk++) {
            float a[8], b[16];
            #pragma unroll
            for (int i = 0; i < 8; i++)
                a[i] = __bfloat162float(As[(tr * 8 + i) * 32 + kk]);
            #pragma unroll
            for (int j = 0; j < 16; j++)
                b[j] = __bfloat162float(Bs[(tc * 16 + j) * 32 + kk]);
            #pragma unroll
            for (int i = 0; i < 8; i++)
                #pragma unroll
                for (int j = 0; j < 16; j++)
                    acc[i][j] = fmaf(a[i], b[j], acc[i][j]);
        }
        __syncthreads();
    }

    #pragma unroll
    for (int i = 0; i < 8; i++) {
        int m = m0 + tr * 8 + i;
        #pragma unroll
        for (int j = 0; j < 16; j++) {
            int n = n0 + tc * 16 + j;
            __nv_bfloat16 v = __hadd(__float2bfloat16(acc[i][j]),
                                     __float2bfloat16(bias[n]));
            out[(size_t)m * Ndim + n] = __bfloat162float(v);
        }
    }
#endif
}

// ============================================================================
// Launch
// ============================================================================

extern "C" void kernel_launch(void* const* d_in, const int* in_sizes, int n_in,
                              void* d_out, int out_size) {
    const float* x    = (const float*)d_in[0];   // [B, S, IN] f32
    const float* wq   = (const float*)d_in[1];   // [OUT, IN] f32 (fp8-representable)
    const float* ws   = (const float*)d_in[2];   // [OUT, 1] f32
    const float* bias = (const float*)d_in[3];   // [OUT] f32
    float* out = (float*)d_out;                  // [B, S, OUT] FP32

    // Convert inputs to bf16 scratch.
    {
        int threads = 256;
        int blocks = (Mdim * Kdim / 4) / threads;  // 16384
        cvt_x_kernel<<<blocks, threads>>>(x);
        cvt_w_kernel<<<blocks, threads>>>(wq, ws);
    }

    cudaFuncSetAttribute(gemm_kernel, cudaFuncAttributeMaxDynamicSharedMemorySize, SMEM_TOTAL);
    dim3 grid(Ndim / NT, Mdim / MT);  // (32, 32)
    gemm_kernel<<<grid, 128, SMEM_TOTAL>>>(out, bias);
}